// round 3
// baseline (speedup 1.0000x reference)
#include <cuda_runtime.h>
#include <cstdint>

// F0Collisions: fused self-consistent-beta + rank-1 VFP diffusion + implicit
// tridiagonal (Chang-Leonard style Bell-Sherlock collision operator).
//
// Design: one WARP per x-row (512 v-bins). Each lane owns 16 contiguous bins.
//  - moments & beta fixed-point: per-lane partial sums + warp butterfly reduce
//  - tridiagonal solve: register SPIKE — each lane Thomas-reduces its 15
//    interior equations to the form x_i = E_i - F_i*x_{l-1} - G_i*x_r, the 32
//    interface unknowns {x_r} form an exactly tridiagonal 32-system solved by
//    5-step warp-shuffle PCR, then register back-substitution.
//  No shared memory, no block barriers.

#define FULLMASK 0xffffffffu

constexpr int   NVC  = 512;
constexpr int   P    = 16;               // bins per lane
constexpr float DVF  = 0.015625f;        // 8/512, exact power of two
constexpr float TWO_PI_F  = (float)6.283185307179586476925287;
constexpr float FOUR_PI_F = (float)12.566370614359172953850574;
constexpr float NUEE = 2.221e-07f;
constexpr float SC_RTOL = 1e-08f;
constexpr float SC_ATOL = 1e-12f;

__device__ __forceinline__ float warp_sum(float x) {
#pragma unroll
    for (int o = 16; o; o >>= 1) x += __shfl_xor_sync(FULLMASK, x, o);
    return x;
}

__global__ __launch_bounds__(256)
void f0collisions_kernel(const float* __restrict__ f0x,
                         const float* __restrict__ dtp,
                         float* __restrict__ out, int nrows)
{
    const int warp_global = (blockIdx.x * blockDim.x + threadIdx.x) >> 5;
    const int lane = threadIdx.x & 31;
    if (warp_global >= nrows) return;

    const int base = lane * P;               // first global v-index of this lane
    const float* frow = f0x + (size_t)warp_global * NVC + base;

    // ---- load 16 f values (4x float4, coalesced) ----
    float f[P];
    {
        const float4* p4 = reinterpret_cast<const float4*>(frow);
#pragma unroll
        for (int q4 = 0; q4 < 4; q4++) {
            float4 t = p4[q4];
            f[4*q4+0]=t.x; f[4*q4+1]=t.y; f[4*q4+2]=t.z; f[4*q4+3]=t.w;
        }
    }

    // ---- moments: S2 = sum f v^2, S4 = sum f v^4 ----
    float s2 = 0.f, s4 = 0.f;
#pragma unroll
    for (int q = 0; q < P; q++) {
        float v  = (base + q + 0.5f) * DVF;   // exact (DV = 2^-6)
        float v2 = v * v, v4 = v2 * v2;
        s2 += f[q] * v2;
        s4 += f[q] * v4;
    }
    s2 = warp_sum(s2);
    s4 = warp_sum(s4);

    const float T_f = s4 / (3.0f * s2);
    float beta = 1.0f / T_f;

    // ---- 3 fixed-point iterations with convergence freeze (matches lax.scan) ----
#pragma unroll
    for (int it = 0; it < 3; it++) {
        float m2 = 0.f, m4 = 0.f;
        const float hb = -0.5f * beta;
#pragma unroll
        for (int q = 0; q < P; q++) {
            float v  = (base + q + 0.5f) * DVF;
            float v2 = v * v;
            float e  = __expf(hb * v2);
            m2 += e * v2;
            m4 += e * v2 * v2;
        }
        m2 = warp_sum(m2);
        m4 = warp_sum(m4);
        float T_M = m4 / (3.0f * m2);
        float bn  = (beta * T_M) / T_f;
        bool done = fabsf(bn - beta) <= (SC_ATOL + SC_RTOL * fabsf(beta));
        beta = done ? beta : bn;
    }

    // ---- rank-1 kernel: inner = 2pi * sum_edges sqrt(eps) f_edge dEps ----
    const float fn0 = __shfl_down_sync(FULLMASK, f[0], 1);  // next lane's f[0]
    float si = 0.f;
#pragma unroll
    for (int q = 0; q < P; q++) {
        int e = base + q;
        float fr = (q < P-1) ? f[q+1] : fn0;
        if (e < NVC - 1) {   // only lane31,q=15 excluded
            float ve = (e + 1) * DVF;            // edge velocity (exact)
            float fe = 0.5f * (f[q] + fr);
            float se = sqrtf(0.5f * ve * ve);    // sqrt(eps_edge)
            si += se * fe * (ve * DVF);
        }
    }
    si = warp_sum(si);
    const float inner  = TWO_PI_F * si;
    const float n4pi   = (FOUR_PI_F * s2) * DVF;
    const float rowfac = inner / (beta * n4pi);   // D = sqrt_eps * rowfac

    const float kk = dtp[0] * NUEE;               // k = dt * NUEE_COEFF

    // ---- edge coefficients w2*lo, w2*hi (Chang-Cooper delta weighting) ----
    float w2lo[P], w2hi[P];
#pragma unroll
    for (int q = 0; q < P; q++) {
        int e = base + q;
        if (e < NVC - 1) {
            float ve = (e + 1) * DVF;
            float se = sqrtf(0.5f * ve * ve);
            float D  = se * rowfac;
            float w  = __fdividef(ve * DVF, D);
            float delta;
            if (fabsf(w) < 1e-6f) delta = 0.5f;
            else delta = __fdividef(1.f, w) - __fdividef(1.f, expm1f(w));
            float DoDV = D * 64.0f;               // D/DV, DV exact pow2
            float lo = ve * delta - DoDV;
            float hi = ve * (1.0f - delta) + DoDV;
            float w2 = ve * ve;
            w2lo[q] = w2 * lo;
            w2hi[q] = w2 * hi;
        } else {
            w2lo[q] = 0.f; w2hi[q] = 0.f;         // padding: matches concat([.,0])
        }
    }
    float loPrev = __shfl_up_sync(FULLMASK, w2lo[P-1], 1);
    float hiPrev = __shfl_up_sync(FULLMASK, w2hi[P-1], 1);
    if (lane == 0) { loPrev = 0.f; hiPrev = 0.f; }  // -> a_0 = 0 exactly

    // tridiagonal row i: a x_{i-1} + b x_i + c x_{i+1} = f_i
    auto coeff = [&](int q, float lom1, float him1, float& a, float& b, float& c) {
        int i = base + q;
        float v  = (i + 0.5f) * DVF;
        float v2 = v * v;
        float inv = __fdividef(1.0f, v2 * DVF);
        a = kk * lom1 * inv;                       // -k*subL
        b = 1.0f - kk * (w2lo[q] - him1) * inv;    // 1 - k*diagL
        c = -kk * w2hi[q] * inv;                   // -k*supL  (0 at i=511)
    };

    // ---- register SPIKE: eliminate 15 interior rows per lane ----
    // x_q = E[q] - F[q]*x_{l-1} - G[q]*x_r  for q=0..14
    float cp[P-1], E[P-1], F[P-1], G[P-1];
    {
        float a, b, c;
        coeff(0, loPrev, hiPrev, a, b, c);
        float w = __fdividef(1.0f, b);
        cp[0] = c * w;
        E[0]  = f[0] * w;
        F[0]  = a * w;        // exactly 0 on lane 0
        G[0]  = 0.f;
    }
#pragma unroll
    for (int q = 1; q < P-1; q++) {
        float a, b, c;
        coeff(q, w2lo[q-1], w2hi[q-1], a, b, c);
        float denom = b - a * cp[q-1];
        float w = __fdividef(1.0f, denom);
        cp[q] = (q < P-2) ? c * w : 0.f;           // M has no superdiag on its last row
        E[q]  = (f[q] - a * E[q-1]) * w;
        F[q]  = (-a * F[q-1]) * w;
        G[q]  = (q == P-2) ? c * w : 0.f;          // rhs c_{r-1} enters only at q=14
    }
#pragma unroll
    for (int q = P-3; q >= 0; q--) {               // back-substitution
        E[q] -= cp[q] * E[q+1];
        F[q] -= cp[q] * F[q+1];
        G[q]  = -cp[q] * G[q+1];
    }

    // ---- reduced 32x32 tridiagonal on the interface unknowns x_r ----
    float a_r, b_r, c_r;
    coeff(P-1, w2lo[P-2], w2hi[P-2], a_r, b_r, c_r);   // row r = base+15
    float E0n = __shfl_down_sync(FULLMASK, E[0], 1);   // next lane's x_l coeffs
    float F0n = __shfl_down_sync(FULLMASK, F[0], 1);
    float G0n = __shfl_down_sync(FULLMASK, G[0], 1);
    float pa = -a_r * F[P-2];                          // 0 on lane 0
    float pb =  b_r - a_r * G[P-2] - c_r * F0n;        // c_r = 0 on lane 31
    float pc = -c_r * G0n;
    float pd =  f[P-1] - a_r * E[P-2] - c_r * E0n;

    // 5-step warp PCR
#pragma unroll
    for (int s = 1; s < 32; s <<= 1) {
        float am = __shfl_up_sync(FULLMASK, pa, s);
        float bm = __shfl_up_sync(FULLMASK, pb, s);
        float cm = __shfl_up_sync(FULLMASK, pc, s);
        float dm = __shfl_up_sync(FULLMASK, pd, s);
        float ap = __shfl_down_sync(FULLMASK, pa, s);
        float bp = __shfl_down_sync(FULLMASK, pb, s);
        float cq = __shfl_down_sync(FULLMASK, pc, s);
        float dq = __shfl_down_sync(FULLMASK, pd, s);
        float k1 = (lane >= s)     ? __fdividef(pa, bm) : 0.f;
        float k2 = (lane + s < 32) ? __fdividef(pc, bp) : 0.f;
        float nb = pb - k1 * cm - k2 * ap;
        float nd = pd - k1 * dm - k2 * dq;
        float na = -k1 * am;
        float nc = -k2 * cq;
        pa = na; pb = nb; pc = nc; pd = nd;
    }
    const float xr = __fdividef(pd, pb);
    float xm = __shfl_up_sync(FULLMASK, xr, 1);        // lane0: multiplied by F=0

    // ---- interior back-substitution + coalesced store ----
    float x[P];
#pragma unroll
    for (int q = 0; q < P-1; q++) x[q] = E[q] - F[q] * xm - G[q] * xr;
    x[P-1] = xr;

    float4* o4 = reinterpret_cast<float4*>(out + (size_t)warp_global * NVC + base);
#pragma unroll
    for (int q4 = 0; q4 < 4; q4++)
        o4[q4] = make_float4(x[4*q4], x[4*q4+1], x[4*q4+2], x[4*q4+3]);
}

extern "C" void kernel_launch(void* const* d_in, const int* in_sizes, int n_in,
                              void* d_out, int out_size)
{
    // metadata order: nu (1), f0x (nx*512), dt (1), v (512)
    const float* f0x = (const float*)d_in[1];
    const float* dtp = (const float*)d_in[2];
    const int nrows = in_sizes[1] / NVC;

    const int threads = 256;                 // 8 warps = 8 rows per block
    const int wpb = threads / 32;
    const int blocks = (nrows + wpb - 1) / wpb;
    f0collisions_kernel<<<blocks, threads>>>(f0x, dtp, (float*)d_out, nrows);
}

// round 4
// speedup vs baseline: 1.6231x; 1.6231x over previous
#include <cuda_runtime.h>
#include <cstdint>

// F0Collisions — fused, algebraically collapsed version.
// Key identity: sqrt(eps_edge) = v_edge / sqrt(2), so the Chang-Cooper Peclet
// number w = C*DV/D is the SAME for every edge of a row -> delta/expm1/divides
// are computed once per row. Edge coefficients become w2lo = ve^3*loK,
// w2hi = ve^3*hiK with per-row scalars. Tridiagonal rows are scaled by v^2*DV
// to eliminate per-point reciprocals. One warp per row, register SPIKE solve.

#define FULLMASK 0xffffffffu

constexpr int   NVC = 512;
constexpr int   P   = 16;                 // bins per lane
constexpr float DVF = 0.015625f;          // 8/512 (exact pow2)
constexpr float NUEE = 2.221e-07f;
constexpr float SC_RTOL = 1e-08f;
constexpr float SC_ATOL = 1e-12f;
constexpr float HALF_INVS2 = 0.3535533905932738f;   // 1/(2*sqrt(2))
constexpr float SQRT2_DV   = 0.0220970869120796f;   // sqrt(2)*DV
constexpr float C64_INVS2  = 45.254833995939045f;   // 64/sqrt(2)

__device__ __forceinline__ float wsum(float x) {
#pragma unroll
    for (int o = 16; o; o >>= 1) x += __shfl_xor_sync(FULLMASK, x, o);
    return x;
}

__global__ __launch_bounds__(256, 2)
void f0collisions_kernel(const float* __restrict__ f0x,
                         const float* __restrict__ dtp,
                         float* __restrict__ out, int nrows)
{
    const int wg   = (blockIdx.x * blockDim.x + threadIdx.x) >> 5;
    const int lane = threadIdx.x & 31;
    if (wg >= nrows) return;

    const int base = lane * P;

    // ---- load 16 f values (coalesced float4) ----
    float f[P];
    {
        const float4* p4 = reinterpret_cast<const float4*>(f0x + (size_t)wg * NVC + base);
#pragma unroll
        for (int q4 = 0; q4 < 4; q4++) {
            float4 t = p4[q4];
            f[4*q4+0]=t.x; f[4*q4+1]=t.y; f[4*q4+2]=t.z; f[4*q4+3]=t.w;
        }
    }

    // ---- v^2 table (registers, reused by every subsequent loop) ----
    const float v0 = (base + 0.5f) * DVF;
    float v2[P];
#pragma unroll
    for (int q = 0; q < P; q++) { float v = v0 + q * DVF; v2[q] = v * v; }

    // ---- fused moments (S2, S4) + rank-1 inner sum (si = sum ve^2 * f_edge) ----
    float s2 = 0.f, s4 = 0.f, si = 0.f;
    const float fn0 = __shfl_down_sync(FULLMASK, f[0], 1);
#pragma unroll
    for (int q = 0; q < P; q++) {
        float v4 = v2[q] * v2[q];
        s2 = fmaf(f[q], v2[q], s2);
        s4 = fmaf(f[q], v4,    s4);
    }
#pragma unroll
    for (int q = 0; q < P-1; q++) {
        float ve = v0 + (q + 0.5f) * DVF;           // edge velocity (base+q+1)*DV
        float fe = 0.5f * (f[q] + f[q+1]);
        si = fmaf(ve * ve, fe, si);
    }
    if (lane != 31) {                               // edge 511 does not exist
        float ve = v0 + 15.5f * DVF;
        float fe = 0.5f * (f[P-1] + fn0);
        si = fmaf(ve * ve, fe, si);
    }
    s2 = wsum(s2); s4 = wsum(s4); si = wsum(si);

    const float T_f   = s4 / (3.0f * s2);
    const float beta0 = 1.0f / T_f;
    float beta = beta0;

    // ---- 3 fixed-point iterations with convergence freeze ----
#pragma unroll
    for (int it = 0; it < 3; it++) {
        float m2 = 0.f, m4 = 0.f;
        const float hb = -0.5f * beta;
#pragma unroll
        for (int q = 0; q < P; q++) {
            float e = __expf(hb * v2[q]);
            float t = e * v2[q];
            m2 += t;
            m4 = fmaf(t, v2[q], m4);
        }
        m2 = wsum(m2); m4 = wsum(m4);
        float T_M = __fdividef(m4, 3.0f * m2);
        float bn  = beta * T_M * beta0;
        bool done = fabsf(bn - beta) <= (SC_ATOL + SC_RTOL * fabsf(beta));
        beta = done ? beta : bn;
    }

    // ---- per-row scalars: D(e) = ve * rowfac / sqrt(2); w is edge-independent ----
    const float rowfac = __fdividef(si * HALF_INVS2, beta * s2);
    const float w = __fdividef(SQRT2_DV, rowfac);
    float delta;
    if (fabsf(w) < 1e-6f) delta = 0.5f;
    else delta = __fdividef(1.f, w) - __fdividef(1.f, expm1f(w));

    const float kk  = dtp[0] * NUEE;
    const float dK  = C64_INVS2 * rowfac;           // (D/DV)/ve
    const float kLo = kk * (delta - dK);            // k * w2lo / ve^3
    const float kHi = kk * ((1.0f - delta) + dK);   // k * w2hi / ve^3

    // ---- Thomas forward sweep, edge coeffs generated inline (rows scaled by v^2*DV) ----
    // Row i:  kLo*ve3_{i-1} * x_{i-1} + (s_i - kLo*ve3_i + kHi*ve3_{i-1}) * x_i
    //         - kHi*ve3_i * x_{i+1} = s_i * f_i
    float vem3;                                     // ve^3 of edge base-1 (local: loK/hiK warp-uniform)
    { float vem = lane * 0.25f; vem3 = (lane == 0) ? 0.f : vem * vem * vem; }
    float ve = v0 + 0.5f * DVF;                     // edge (base+1)*DV

    float cp[P-1], E[P-1], F[P-1], G[P-1];
    float Eprev = 0.f, Fprev = 0.f, cpPrev = 0.f;
#pragma unroll
    for (int q = 0; q < P-1; q++) {
        float s   = v2[q] * DVF;
        float ve3 = ve * (ve * ve);
        float a   = kLo * vem3;
        float b   = fmaf(-kLo, ve3, s);
        b         = fmaf(kHi, vem3, b);
        float c   = -kHi * ve3;
        float d   = s * f[q];
        float denom = (q == 0) ? b : fmaf(-a, cpPrev, b);
        float wv  = __fdividef(1.f, denom);
        float cpv = (q == P-2) ? 0.f : c * wv;
        float Ev  = (q == 0) ? d * wv : (d - a * Eprev) * wv;
        float Fv  = (q == 0) ? a * wv : (-a * Fprev) * wv;
        cp[q] = cpv; E[q] = Ev; F[q] = Fv;
        G[q]  = (q == P-2) ? c * wv : 0.f;
        cpPrev = cpv; Eprev = Ev; Fprev = Fv;
        vem3 = ve3; ve += DVF;
    }
#pragma unroll
    for (int q = P-3; q >= 0; q--) {                // interior back-substitution
        E[q] = fmaf(-cp[q], E[q+1], E[q]);
        F[q] = fmaf(-cp[q], F[q+1], F[q]);
        G[q] = -cp[q] * G[q+1];
    }

    // ---- interface row r = base+15 ----
    float s_r  = v2[P-1] * DVF;
    float ve3r = (lane == 31) ? 0.f : ve * (ve * ve);   // edge 511 absent
    float a_r  = kLo * vem3;
    float b_r  = fmaf(-kLo, ve3r, s_r);
    b_r        = fmaf(kHi, vem3, b_r);
    float c_r  = -kHi * ve3r;                           // exactly 0 on lane 31
    float d_r  = s_r * f[P-1];

    float E0n = __shfl_down_sync(FULLMASK, E[0], 1);
    float F0n = __shfl_down_sync(FULLMASK, F[0], 1);
    float G0n = __shfl_down_sync(FULLMASK, G[0], 1);
    float pa = -a_r * F[P-2];                           // 0 on lane 0
    float pb =  b_r - a_r * G[P-2] - c_r * F0n;
    float pc = -c_r * G0n;
    float pd =  d_r - a_r * E[P-2] - c_r * E0n;

    // ---- 5-step warp PCR on the 32 interface unknowns ----
#pragma unroll
    for (int s = 1; s < 32; s <<= 1) {
        float am = __shfl_up_sync(FULLMASK, pa, s);
        float bm = __shfl_up_sync(FULLMASK, pb, s);
        float cm = __shfl_up_sync(FULLMASK, pc, s);
        float dm = __shfl_up_sync(FULLMASK, pd, s);
        float ap = __shfl_down_sync(FULLMASK, pa, s);
        float bp = __shfl_down_sync(FULLMASK, pb, s);
        float cq = __shfl_down_sync(FULLMASK, pc, s);
        float dq = __shfl_down_sync(FULLMASK, pd, s);
        float k1 = (lane >= s)     ? __fdividef(pa, bm) : 0.f;
        float k2 = (lane + s < 32) ? __fdividef(pc, bp) : 0.f;
        float nb = pb - k1 * cm - k2 * ap;
        float nd = pd - k1 * dm - k2 * dq;
        pa = -k1 * am;
        pc = -k2 * cq;
        pb = nb; pd = nd;
    }
    const float xr = __fdividef(pd, pb);
    float xm = __shfl_up_sync(FULLMASK, xr, 1);         // lane0: multiplied by F=0

    // ---- final back-substitution + coalesced store ----
    float x[P];
#pragma unroll
    for (int q = 0; q < P-1; q++) x[q] = E[q] - F[q] * xm - G[q] * xr;
    x[P-1] = xr;

    float4* o4 = reinterpret_cast<float4*>(out + (size_t)wg * NVC + base);
#pragma unroll
    for (int q4 = 0; q4 < 4; q4++)
        o4[q4] = make_float4(x[4*q4], x[4*q4+1], x[4*q4+2], x[4*q4+3]);
}

extern "C" void kernel_launch(void* const* d_in, const int* in_sizes, int n_in,
                              void* d_out, int out_size)
{
    // metadata order: nu (1), f0x (nx*512), dt (1), v (512)
    const float* f0x = (const float*)d_in[1];
    const float* dtp = (const float*)d_in[2];
    const int nrows  = in_sizes[1] / NVC;

    const int threads = 256;               // 8 warps = 8 rows per block
    const int wpb = threads / 32;
    const int blocks = (nrows + wpb - 1) / wpb;
    f0collisions_kernel<<<blocks, threads>>>(f0x, dtp, (float*)d_out, nrows);
}

// round 5
// speedup vs baseline: 1.8529x; 1.1416x over previous
#include <cuda_runtime.h>
#include <cstdint>

// F0Collisions — fused Chang-Cooper/Bell-Sherlock collision step.
// One warp per x-row (512 v-bins), 16 bins/lane, register SPIKE tridiagonal
// solve (Thomas per-lane + 5-step warp PCR on the 32 interface unknowns).
// R5 changes: G-array eliminated (scalar hat-chain), f/E register aliasing,
// incremental v^2 (no table), geometric exp recurrence in the beta loop,
// reciprocal-shuffled PCR, 0.5 folded into row constant. Targets 3 CTAs/SM.

#define FULLMASK 0xffffffffu

constexpr int   NVC = 512;
constexpr int   P   = 16;                 // bins per lane
constexpr float DVF = 0.015625f;          // 8/512 (exact pow2)
constexpr float NUEE = 2.221e-07f;
constexpr float SC_RTOL = 1e-08f;
constexpr float SC_ATOL = 1e-12f;
constexpr float QUARTER_INVS2 = 0.17677669529663687f; // 1/(4*sqrt(2)) (0.5 of f_edge folded in)
constexpr float SQRT2_DV      = 0.02209708691207961f; // sqrt(2)*DV
constexpr float C64_INVS2     = 45.254833995939045f;  // 64/sqrt(2)

__device__ __forceinline__ float wsum(float x) {
#pragma unroll
    for (int o = 16; o; o >>= 1) x += __shfl_xor_sync(FULLMASK, x, o);
    return x;
}

__global__ __launch_bounds__(256, 3)
void f0collisions_kernel(const float* __restrict__ f0x,
                         const float* __restrict__ dtp,
                         float* __restrict__ out, int nrows)
{
    const int wg   = (blockIdx.x * blockDim.x + threadIdx.x) >> 5;
    const int lane = threadIdx.x & 31;
    if (wg >= nrows) return;

    const int base = lane * P;

    // fE[] holds f on entry; becomes E during the forward sweep; becomes x at the end.
    float fE[P];
    {
        const float4* p4 = reinterpret_cast<const float4*>(f0x + (size_t)wg * NVC + base);
#pragma unroll
        for (int q4 = 0; q4 < 4; q4++) {
            float4 t = p4[q4];
            fE[4*q4+0]=t.x; fE[4*q4+1]=t.y; fE[4*q4+2]=t.z; fE[4*q4+3]=t.w;
        }
    }

    const float v0   = (base + 0.5f) * DVF;       // exact
    const float v0sq = v0 * v0;
    const float dv20 = fmaf(2.0f * DVF, v0, DVF * DVF);   // (v+DV)^2 - v^2 at q=0
    const float c2   = 2.0f * DVF * DVF;

    // ---- moments S2 = sum f v^2, S4 = sum f v^4 (incremental v^2) ----
    float s2 = 0.f, s4 = 0.f;
    {
        float v2 = v0sq, d2 = dv20;
#pragma unroll
        for (int q = 0; q < P; q++) {
            float t = fE[q] * v2;
            s2 += t;
            s4 = fmaf(t, v2, s4);
            v2 += d2; d2 += c2;
        }
    }
    // ---- rank-1 inner sum: si = sum_edges ve^2 * (f_q + f_{q+1})  (0.5 folded out) ----
    float si = 0.f;
    {
        const float fn0 = __shfl_down_sync(FULLMASK, fE[0], 1);
        float ve = v0 + 0.5f * DVF;               // edge (base+1)*DV, exact
#pragma unroll
        for (int q = 0; q < P-1; q++) {
            si = fmaf(ve * ve, fE[q] + fE[q+1], si);
            ve += DVF;
        }
        if (lane != 31)                            // edge 511 does not exist
            si = fmaf(ve * ve, fE[P-1] + fn0, si);
    }
    s2 = wsum(s2); s4 = wsum(s4); si = wsum(si);

    const float T_f   = s4 / (3.0f * s2);
    const float beta0 = 1.0f / T_f;
    float beta = beta0;

    // ---- 3 fixed-point iterations; exp via geometric recurrence (3 MUFU/iter) ----
#pragma unroll
    for (int it = 0; it < 3; it++) {
        const float hb = -0.5f * beta;
        float e = __expf(hb * v0sq);
        float r = __expf(hb * dv20);
        const float S = __expf(hb * c2);
        float v2 = v0sq, d2 = dv20;
        float m2 = 0.f, m4 = 0.f;
#pragma unroll
        for (int q = 0; q < P; q++) {
            float t = e * v2;
            m2 += t;
            m4 = fmaf(t, v2, m4);
            e *= r;
            r *= S;
            v2 += d2; d2 += c2;
        }
        m2 = wsum(m2); m4 = wsum(m4);
        float T_M = __fdividef(m4, 3.0f * m2);
        float bn  = beta * T_M * beta0;
        bool done = fabsf(bn - beta) <= (SC_ATOL + SC_RTOL * fabsf(beta));
        beta = done ? beta : bn;
    }

    // ---- per-row scalars: D(e) = ve*rowfac/sqrt(2); Peclet w is edge-independent ----
    const float rowfac = __fdividef(si * QUARTER_INVS2, beta * s2);
    const float w = __fdividef(SQRT2_DV, rowfac);
    float delta;
    if (fabsf(w) < 1e-6f) delta = 0.5f;
    else delta = __fdividef(1.f, w) - __fdividef(1.f, expm1f(w));

    const float kk  = dtp[0] * NUEE;
    const float dK  = C64_INVS2 * rowfac;          // (D/DV)/ve
    const float kLo = kk * (delta - dK);           // k * w2lo / ve^3
    const float kHi = kk * ((1.0f - delta) + dK);  // k * w2hi / ve^3

    // ---- Thomas forward sweep (rows scaled by v^2*DV), coeffs generated inline ----
    float cp[P-1], F[P-1];
    float vem3;
    { float vem = lane * 0.25f; vem3 = (lane == 0) ? 0.f : vem * vem * vem; }
    float ve = v0 + 0.5f * DVF;
    float v2 = v0sq, d2 = dv20;
    float cpPrev = 0.f, Eprev = 0.f, Fprev = 0.f;
#pragma unroll
    for (int q = 0; q < P-1; q++) {
        float s   = v2 * DVF;
        float ve3 = ve * (ve * ve);
        float a   = kLo * vem3;
        float b   = fmaf(-kLo, ve3, s);
        b         = fmaf(kHi, vem3, b);
        float c   = -kHi * ve3;
        float d   = s * fE[q];
        float denom = fmaf(-a, cpPrev, b);          // q=0: cpPrev=0
        float wv  = __fdividef(1.f, denom);
        float cpv = c * wv;
        float Ev  = fmaf(-a, Eprev, d) * wv;
        float Fv  = (q == 0) ? a * wv : (-a * Fprev) * wv;
        cp[q] = cpv; fE[q] = Ev; F[q] = Fv;         // fE[q]: f consumed -> now E
        cpPrev = cpv; Eprev = Ev; Fprev = Fv;
        vem3 = ve3; ve += DVF; v2 += d2; d2 += c2;
    }

    // ---- interface row r = base+15 ----
    float s_r  = v2 * DVF;
    float ve3r = (lane == 31) ? 0.f : ve * (ve * ve);   // edge 511 absent
    float a_r  = kLo * vem3;
    float b_r  = fmaf(-kLo, ve3r, s_r);
    b_r        = fmaf(kHi, vem3, b_r);
    float c_r  = -kHi * ve3r;                           // exactly 0 on lane 31
    float d_r  = s_r * fE[P-1];                         // fE[P-1] still raw f

    // ---- hat chain: compose x_0 = Eh - Fh*xm - Gh*xr (scalars only) ----
    float Eh = Eprev, Fh = Fprev, Gh = cpPrev;          // values at q=P-2
#pragma unroll
    for (int q = P-3; q >= 0; q--) {
        Eh = fmaf(-cp[q], Eh, fE[q]);
        Fh = fmaf(-cp[q], Fh, F[q]);
        Gh = -cp[q] * Gh;
    }
    const float E0n = __shfl_down_sync(FULLMASK, Eh, 1);
    const float F0n = __shfl_down_sync(FULLMASK, Fh, 1);
    const float G0n = __shfl_down_sync(FULLMASK, Gh, 1);

    float pa = -a_r * Fprev;                            // 0 on lane 0
    float pb =  b_r - a_r * cpPrev - c_r * F0n;
    float pc = -c_r * G0n;
    float pd =  d_r - a_r * Eprev - c_r * E0n;

    // ---- 5-step warp PCR (reciprocal shuffled: 1 RCP per step) ----
#pragma unroll
    for (int s = 1; s < 32; s <<= 1) {
        float rb = __fdividef(1.f, pb);
        float am = __shfl_up_sync(FULLMASK, pa, s);
        float cm = __shfl_up_sync(FULLMASK, pc, s);
        float dm = __shfl_up_sync(FULLMASK, pd, s);
        float rm = __shfl_up_sync(FULLMASK, rb, s);
        float ap = __shfl_down_sync(FULLMASK, pa, s);
        float cq = __shfl_down_sync(FULLMASK, pc, s);
        float dq = __shfl_down_sync(FULLMASK, pd, s);
        float rp = __shfl_down_sync(FULLMASK, rb, s);
        float k1 = (lane >= s)     ? pa * rm : 0.f;
        float k2 = (lane + s < 32) ? pc * rp : 0.f;
        pb = pb - k1 * cm - k2 * ap;
        pd = pd - k1 * dm - k2 * dq;
        pa = -k1 * am;
        pc = -k2 * cq;
    }
    const float xr = __fdividef(pd, pb);
    const float xm = __shfl_up_sync(FULLMASK, xr, 1);   // lane0: multiplied by F=0

    // ---- direct backward substitution (reference Thomas form) ----
    float xnext = xr;
    fE[P-1] = xr;
#pragma unroll
    for (int q = P-2; q >= 0; q--) {
        float dp = fmaf(-F[q], xm, fE[q]);              // E_q - F_q*xm
        xnext = fmaf(-cp[q], xnext, dp);
        fE[q] = xnext;
    }

    float4* o4 = reinterpret_cast<float4*>(out + (size_t)wg * NVC + base);
#pragma unroll
    for (int q4 = 0; q4 < 4; q4++)
        o4[q4] = make_float4(fE[4*q4], fE[4*q4+1], fE[4*q4+2], fE[4*q4+3]);
}

extern "C" void kernel_launch(void* const* d_in, const int* in_sizes, int n_in,
                              void* d_out, int out_size)
{
    // metadata order: nu (1), f0x (nx*512), dt (1), v (512)
    const float* f0x = (const float*)d_in[1];
    const float* dtp = (const float*)d_in[2];
    const int nrows  = in_sizes[1] / NVC;

    const int threads = 256;               // 8 warps = 8 rows per block
    const int wpb = threads / 32;
    const int blocks = (nrows + wpb - 1) / wpb;
    f0collisions_kernel<<<blocks, threads>>>(f0x, dtp, (float*)d_out, nrows);
}